// round 1
// baseline (speedup 1.0000x reference)
#include <cuda_runtime.h>
#include <stdint.h>

// Problem constants (validated against in_sizes at launch; scratch sized for max)
#define SPAN   8
#define DIM    192
#define DIM4   48          // DIM / 4
#define KCB    512
#define MAX_NS 16384       // B*T/SPAN
#define MAX_N  131072      // B*T

// -------- device scratch (no allocations allowed) --------
__device__ float        g_pooled[MAX_NS * DIM];   // 12.6 MB
__device__ int          g_idx[MAX_NS];
__device__ float        g_c2[KCB];
__device__ float        g_partial[MAX_NS / 32];   // one per K3 block
__device__ unsigned int g_count;

// ============================================================
// K0: codebook squared norms + reset boundary counter
// ============================================================
__global__ void k0_c2(const float* __restrict__ codebook, int K)
{
    int k = blockIdx.x * blockDim.x + threadIdx.x;
    if (k == 0) g_count = 0u;
    if (k < K) {
        const float4* row = (const float4*)(codebook + (size_t)k * DIM);
        float s = 0.f;
#pragma unroll
        for (int i = 0; i < DIM4; i++) {
            float4 v = row[i];
            s += v.x * v.x + v.y * v.y + v.z * v.z + v.w * v.w;
        }
        g_c2[k] = s;
    }
}

// ============================================================
// K1: single pass over x -> pooled, boundaries, boundary count
// Block: 256 threads = 32 segments x 8 lane-groups.
// Thread (s_local = tid>>3, g = tid&7) owns segment s, dims {g, g+8, ..., g+40} (float4 units).
// Pooling is fully thread-local; boundary logit reduced over the 8-lane group.
// ============================================================
__global__ void k1_pool_boundary(const float4* __restrict__ x4,
                                 const float4* __restrict__ w4,
                                 const float*  __restrict__ bbias,
                                 float* __restrict__ bnd_out)
{
    int tid = threadIdx.x;
    int s_local = tid >> 3;
    int g = tid & 7;
    int s = blockIdx.x * 32 + s_local;

    float4 wv[6];
#pragma unroll
    for (int i = 0; i < 6; i++) wv[i] = __ldg(&w4[g + 8 * i]);

    float4 pool[6];
#pragma unroll
    for (int i = 0; i < 6; i++) pool[i] = make_float4(0.f, 0.f, 0.f, 0.f);

    float part[SPAN];
    int tokBase = s * SPAN;

#pragma unroll
    for (int j = 0; j < SPAN; j++) {
        const float4* row = x4 + (size_t)(tokBase + j) * DIM4;
        float pj = 0.f;
#pragma unroll
        for (int i = 0; i < 6; i++) {
            float4 v = row[g + 8 * i];
            pool[i].x += v.x; pool[i].y += v.y; pool[i].z += v.z; pool[i].w += v.w;
            pj += v.x * wv[i].x + v.y * wv[i].y + v.z * wv[i].z + v.w * wv[i].w;
        }
        part[j] = pj;
    }

    // write pooled (mean)
    float4* pooled4 = (float4*)g_pooled;
#pragma unroll
    for (int i = 0; i < 6; i++) {
        float4 p = pool[i];
        p.x *= 0.125f; p.y *= 0.125f; p.z *= 0.125f; p.w *= 0.125f;
        pooled4[(size_t)s * DIM4 + g + 8 * i] = p;
    }

    // butterfly-sum logit partials within each 8-lane group
#pragma unroll
    for (int m = 1; m < 8; m <<= 1) {
#pragma unroll
        for (int j = 0; j < SPAN; j++)
            part[j] += __shfl_xor_sync(0xffffffffu, part[j], m);
    }

    float bb = __ldg(bbias);
    float logit = part[g] + bb;                // this lane handles token tokBase+g
    float b = (logit > 0.f) ? 1.f : 0.f;
    bnd_out[tokBase + g] = b;

    unsigned bal = __ballot_sync(0xffffffffu, b > 0.f);
    if ((tid & 31) == 0) atomicAdd(&g_count, (unsigned)__popc(bal));
}

// ============================================================
// K2: VQ distance GEMM + fused argmin
// Block tile: 64 segments x all 512 codes (8 chunks of 64 codes in smem).
// 256 threads as 16(ty: seg groups of 4) x 16(tx: code groups of 4).
// score = |c|^2 - 2 p.c   (|p|^2 constant per segment -> dropped, safe for argmin)
// ============================================================
__global__ void k2_vq(const float* __restrict__ codebook, int segTotal)
{
    extern __shared__ float smem[];
    float* As  = smem;                    // [64][192]
    float* Bs  = As + 64 * DIM;           // [192][68] k-major, padded stride 68
    float* c2s = Bs + DIM * 68;           // [64]

    int tid = threadIdx.x;
    int ty = tid >> 4;
    int tx = tid & 15;
    int segBase = blockIdx.x * 64;

    // load pooled tile (coalesced float4)
    {
        const float4* p4 = (const float4*)g_pooled;
        float4* As4 = (float4*)As;
        for (int i = tid; i < 64 * DIM4; i += 256)
            As4[i] = p4[(size_t)segBase * DIM4 + i];
    }

    float best[4];
    int   bidx[4];
#pragma unroll
    for (int i = 0; i < 4; i++) { best[i] = 3.4e38f; bidx[i] = 0; }

    for (int cb = 0; cb < KCB; cb += 64) {
        __syncthreads();   // As ready (first iter) / previous compute done
        // load 64-code chunk, transposed to k-major [d][code]
        for (int i = tid; i < 64 * DIM; i += 256) {
            int r = i / DIM;
            int d = i - r * DIM;
            Bs[d * 68 + r] = codebook[(size_t)(cb + r) * DIM + d];
        }
        if (tid < 64) c2s[tid] = g_c2[cb + tid];
        __syncthreads();

        float acc[4][4];
#pragma unroll
        for (int i = 0; i < 4; i++)
#pragma unroll
            for (int j = 0; j < 4; j++) acc[i][j] = 0.f;

#pragma unroll 4
        for (int kk = 0; kk < DIM; kk += 4) {
            float4 Av[4], Bv[4];
#pragma unroll
            for (int i = 0; i < 4; i++)
                Av[i] = *(const float4*)&As[(4 * ty + i) * DIM + kk];
#pragma unroll
            for (int k = 0; k < 4; k++)
                Bv[k] = *(const float4*)&Bs[(kk + k) * 68 + 4 * tx];
#pragma unroll
            for (int i = 0; i < 4; i++) {
                acc[i][0] += Av[i].x * Bv[0].x + Av[i].y * Bv[1].x + Av[i].z * Bv[2].x + Av[i].w * Bv[3].x;
                acc[i][1] += Av[i].x * Bv[0].y + Av[i].y * Bv[1].y + Av[i].z * Bv[2].y + Av[i].w * Bv[3].y;
                acc[i][2] += Av[i].x * Bv[0].z + Av[i].y * Bv[1].z + Av[i].z * Bv[2].z + Av[i].w * Bv[3].z;
                acc[i][3] += Av[i].x * Bv[0].w + Av[i].y * Bv[1].w + Av[i].z * Bv[2].w + Av[i].w * Bv[3].w;
            }
        }

        // fold into running argmin (ascending code index + strict '<' => first-min tie-break)
#pragma unroll
        for (int i = 0; i < 4; i++) {
#pragma unroll
            for (int j = 0; j < 4; j++) {
                float sc = c2s[4 * tx + j] - 2.f * acc[i][j];
                int ci = cb + 4 * tx + j;
                if (sc < best[i] || (sc == best[i] && ci < bidx[i])) { best[i] = sc; bidx[i] = ci; }
            }
        }
    }

    // reduce argmin across the 16 tx lanes (width-16 shfl, first-min tie-break)
#pragma unroll
    for (int off = 8; off >= 1; off >>= 1) {
#pragma unroll
        for (int i = 0; i < 4; i++) {
            float ob = __shfl_down_sync(0xffffffffu, best[i], off, 16);
            int   oi = __shfl_down_sync(0xffffffffu, bidx[i], off, 16);
            if (ob < best[i] || (ob == best[i] && oi < bidx[i])) { best[i] = ob; bidx[i] = oi; }
        }
    }
    if (tx == 0) {
#pragma unroll
        for (int i = 0; i < 4; i++) {
            int s = segBase + 4 * ty + i;
            if (s < segTotal) g_idx[s] = bidx[i];
        }
    }
}

// ============================================================
// K3: scatter quantized codewords to token resolution, idx_out,
//     and per-block partial of sum((c - p)^2)  (deterministic tree)
// Same thread mapping as K1: 32 segs x 8 groups per block.
// ============================================================
__global__ void k3_scatter(const float4* __restrict__ cb4,
                           float4* __restrict__ q4,
                           float*  __restrict__ idx_out)
{
    __shared__ float red[256];
    int tid = threadIdx.x;
    int s_local = tid >> 3;
    int g = tid & 7;
    int s = blockIdx.x * 32 + s_local;

    int ci = g_idx[s];
    const float4* pooled4 = (const float4*)g_pooled;

    float4 c[6];
    float ssum = 0.f;
#pragma unroll
    for (int i = 0; i < 6; i++) {
        c[i] = __ldg(&cb4[(size_t)ci * DIM4 + g + 8 * i]);
        float4 p = pooled4[(size_t)s * DIM4 + g + 8 * i];
        float dx = c[i].x - p.x, dy = c[i].y - p.y, dz = c[i].z - p.z, dw = c[i].w - p.w;
        ssum += dx * dx + dy * dy + dz * dz + dw * dw;
    }

    int tokBase = s * SPAN;
#pragma unroll
    for (int j = 0; j < SPAN; j++) {
        float4* dst = q4 + (size_t)(tokBase + j) * DIM4;
#pragma unroll
        for (int i = 0; i < 6; i++)
            dst[g + 8 * i] = c[i];
    }
    idx_out[tokBase + g] = (float)ci;

    red[tid] = ssum;
    __syncthreads();
#pragma unroll
    for (int st = 128; st > 0; st >>= 1) {
        if (tid < st) red[tid] += red[tid + st];
        __syncthreads();
    }
    if (tid == 0) g_partial[blockIdx.x] = red[0];
}

// ============================================================
// K4: finalize scalar loss (ordered double accumulation -> deterministic)
// ============================================================
__global__ void k4_final(int nPartial, long nsD, long nTok, float* __restrict__ loss_out)
{
    if (threadIdx.x == 0 && blockIdx.x == 0) {
        double s = 0.0;
        for (int i = 0; i < nPartial; i++) s += (double)g_partial[i];
        double e_latent = s / (double)nsD;
        double bmean = (double)g_count / (double)nTok;
        double d = bmean - 0.125;          // target_rate = 1/SPAN
        *loss_out = (float)(0.25 * e_latent + 0.01 * d * d);
    }
}

// ============================================================
// launch
// inputs: x [B,T,D] f32, codebook [K,D] f32, boundary_w [D] f32, boundary_b [1] f32
// output (assumed concat, f32): q_out [B*T*D] | total_loss [1] | idx_out [B*T] | boundaries [B*T]
// ============================================================
extern "C" void kernel_launch(void* const* d_in, const int* in_sizes, int n_in,
                              void* d_out, int out_size)
{
    const float* x   = (const float*)d_in[0];
    const float* cbk = (const float*)d_in[1];
    const float* bw  = (const float*)d_in[2];
    const float* bb  = (const float*)d_in[3];

    int  Dd   = in_sizes[2];                 // 192
    int  K    = in_sizes[1] / Dd;            // 512
    long nTok = (long)in_sizes[0] / Dd;      // 131072
    long NS   = nTok / SPAN;                 // 16384

    float* q_out    = (float*)d_out;
    float* loss_out = q_out + nTok * (long)Dd;
    float* idx_out  = loss_out + 1;
    float* bnd_out  = idx_out + nTok;

    static bool attr_set = false;
    const int smem2 = (64 * DIM + DIM * 68 + 64) * (int)sizeof(float);  // 101,632 B
    if (!attr_set) {
        cudaFuncSetAttribute(k2_vq, cudaFuncAttributeMaxDynamicSharedMemorySize, smem2);
        attr_set = true;
    }

    k0_c2<<<(K + 255) / 256, 256>>>(cbk, K);
    k1_pool_boundary<<<(int)(NS / 32), 256>>>((const float4*)x, (const float4*)bw, bb, bnd_out);
    k2_vq<<<(int)(NS / 64), 256, smem2>>>(cbk, (int)NS);
    k3_scatter<<<(int)(NS / 32), 256>>>((const float4*)cbk, (float4*)q_out, idx_out);
    k4_final<<<1, 32>>>((int)(NS / 32), NS * (long)Dd, nTok, loss_out);
}

// round 3
// speedup vs baseline: 1.2235x; 1.2235x over previous
#include <cuda_runtime.h>
#include <stdint.h>

// Problem constants
#define SPAN   8
#define DIM    192
#define DIM4   48          // DIM / 4
#define KCB    512
#define MAX_NS 16384       // B*T/SPAN
#define MAX_N  131072      // B*T

// -------- device scratch (no allocations allowed) --------
__device__ float        g_pooled[MAX_NS * DIM];   // 12.6 MB
__device__ int          g_idx[MAX_NS];
__device__ float        g_c2[KCB];
__device__ float        g_partial[MAX_NS / 32];
__device__ unsigned int g_count;

// ---- packed fp32x2 helpers (Blackwell FFMA2 path) ----
__device__ __forceinline__ unsigned long long pack2(float x) {
    unsigned long long r;
    asm("mov.b64 %0, {%1, %1};" : "=l"(r) : "f"(x));
    return r;
}
__device__ __forceinline__ void fma2(unsigned long long& d,
                                     unsigned long long a, unsigned long long b) {
    asm("fma.rn.f32x2 %0, %1, %2, %0;" : "+l"(d) : "l"(a), "l"(b));
}
__device__ __forceinline__ void unpack2(unsigned long long v, float& lo, float& hi) {
    asm("mov.b64 {%0, %1}, %2;" : "=f"(lo), "=f"(hi) : "l"(v));
}

// ============================================================
// K0: codebook squared norms + reset boundary counter
// ============================================================
__global__ void k0_c2(const float* __restrict__ codebook, int K)
{
    int k = blockIdx.x * blockDim.x + threadIdx.x;
    if (k == 0) g_count = 0u;
    if (k < K) {
        const float4* row = (const float4*)(codebook + (size_t)k * DIM);
        float s = 0.f;
#pragma unroll
        for (int i = 0; i < DIM4; i++) {
            float4 v = row[i];
            s += v.x * v.x + v.y * v.y + v.z * v.z + v.w * v.w;
        }
        g_c2[k] = s;
    }
}

// ============================================================
// K1: single pass over x -> pooled, boundaries, boundary count
// Block: 256 threads = 32 segments x 8 lane-groups.
// ============================================================
__global__ void k1_pool_boundary(const float4* __restrict__ x4,
                                 const float4* __restrict__ w4,
                                 const float*  __restrict__ bbias,
                                 float* __restrict__ bnd_out)
{
    int tid = threadIdx.x;
    int s_local = tid >> 3;
    int g = tid & 7;
    int s = blockIdx.x * 32 + s_local;

    float4 wv[6];
#pragma unroll
    for (int i = 0; i < 6; i++) wv[i] = __ldg(&w4[g + 8 * i]);

    float4 pool[6];
#pragma unroll
    for (int i = 0; i < 6; i++) pool[i] = make_float4(0.f, 0.f, 0.f, 0.f);

    float part[SPAN];
    int tokBase = s * SPAN;

#pragma unroll
    for (int j = 0; j < SPAN; j++) {
        const float4* row = x4 + (size_t)(tokBase + j) * DIM4;
        float pj = 0.f;
#pragma unroll
        for (int i = 0; i < 6; i++) {
            float4 v = row[g + 8 * i];
            pool[i].x += v.x; pool[i].y += v.y; pool[i].z += v.z; pool[i].w += v.w;
            pj += v.x * wv[i].x + v.y * wv[i].y + v.z * wv[i].z + v.w * wv[i].w;
        }
        part[j] = pj;
    }

    float4* pooled4 = (float4*)g_pooled;
#pragma unroll
    for (int i = 0; i < 6; i++) {
        float4 p = pool[i];
        p.x *= 0.125f; p.y *= 0.125f; p.z *= 0.125f; p.w *= 0.125f;
        pooled4[(size_t)s * DIM4 + g + 8 * i] = p;
    }

#pragma unroll
    for (int m = 1; m < 8; m <<= 1) {
#pragma unroll
        for (int j = 0; j < SPAN; j++)
            part[j] += __shfl_xor_sync(0xffffffffu, part[j], m);
    }

    float bb = __ldg(bbias);
    float logit = part[g] + bb;
    float b = (logit > 0.f) ? 1.f : 0.f;
    bnd_out[tokBase + g] = b;

    unsigned bal = __ballot_sync(0xffffffffu, b > 0.f);
    if ((tid & 31) == 0) atomicAdd(&g_count, (unsigned)__popc(bal));
}

// ============================================================
// K2 v2: VQ distance GEMM + fused argmin
//   Block tile: 128 segs x 512 codes (4 chunks of 128), K=192 resident.
//   smem: As[192][128] k-major (pooled, loaded once),
//         Bs[192][128] k-major (codebook chunk, streamed), c2s[512].
//   256 threads = 16 ty (seg-groups of 8) x 16 tx (code-groups of 8).
//   Per k: 2 LDS.128 (A) + 2 LDS.128 (B) + 8 pack + 32 fma.rn.f32x2.
//   score = |c|^2 - 2 p.c (|p|^2 dropped; safe for argmin).
// ============================================================
__global__ void __launch_bounds__(256, 1) k2_vq(const float4* __restrict__ cb4, int segTotal)
{
    extern __shared__ float smem[];
    float* As  = smem;                 // 192*128
    float* Bs  = As + 192 * 128;       // 192*128
    float* c2s = Bs + 192 * 128;       // 512

    int tid = threadIdx.x;
    int ty = tid >> 4;
    int tx = tid & 15;
    int segBase = blockIdx.x * 128;

    // c2 table
    for (int i = tid; i < KCB; i += 256) c2s[i] = g_c2[i];

    // ---- load pooled tile, transpose to k-major As[k][m] ----
    {
        const float4* p4 = (const float4*)g_pooled;
        for (int it = 0; it < 6; it++) {
            int item = tid + it * 256;
            int m_grp = item & 31;
            int kq = item >> 5;
            float4 v0 = p4[(size_t)(segBase + m_grp * 4 + 0) * DIM4 + kq];
            float4 v1 = p4[(size_t)(segBase + m_grp * 4 + 1) * DIM4 + kq];
            float4 v2 = p4[(size_t)(segBase + m_grp * 4 + 2) * DIM4 + kq];
            float4 v3 = p4[(size_t)(segBase + m_grp * 4 + 3) * DIM4 + kq];
            const float* a0 = (const float*)&v0;
            const float* a1 = (const float*)&v1;
            const float* a2 = (const float*)&v2;
            const float* a3 = (const float*)&v3;
#pragma unroll
            for (int u = 0; u < 4; u++) {
                *(float4*)&As[(kq * 4 + u) * 128 + m_grp * 4] =
                    make_float4(a0[u], a1[u], a2[u], a3[u]);
            }
        }
    }

    float best[8];
    int   bidx[8];
#pragma unroll
    for (int i = 0; i < 8; i++) { best[i] = 3.4e38f; bidx[i] = 0; }

    for (int nc = 0; nc < 4; nc++) {
        __syncthreads();   // As ready (nc==0) / previous chunk's compute done

        // ---- load codebook chunk, transpose to k-major Bs[k][n] ----
        int cbBase = nc * 128;
        for (int it = 0; it < 6; it++) {
            int item = tid + it * 256;
            int n_grp = item & 31;
            int kq = item >> 5;
            float4 v0 = cb4[(size_t)(cbBase + n_grp * 4 + 0) * DIM4 + kq];
            float4 v1 = cb4[(size_t)(cbBase + n_grp * 4 + 1) * DIM4 + kq];
            float4 v2 = cb4[(size_t)(cbBase + n_grp * 4 + 2) * DIM4 + kq];
            float4 v3 = cb4[(size_t)(cbBase + n_grp * 4 + 3) * DIM4 + kq];
            const float* b0 = (const float*)&v0;
            const float* b1 = (const float*)&v1;
            const float* b2 = (const float*)&v2;
            const float* b3 = (const float*)&v3;
#pragma unroll
            for (int u = 0; u < 4; u++) {
                *(float4*)&Bs[(kq * 4 + u) * 128 + n_grp * 4] =
                    make_float4(b0[u], b1[u], b2[u], b3[u]);
            }
        }
        __syncthreads();

        unsigned long long acc[8][4];
#pragma unroll
        for (int i = 0; i < 8; i++)
#pragma unroll
            for (int j = 0; j < 4; j++) acc[i][j] = 0ull;

#pragma unroll 4
        for (int k = 0; k < DIM; k++) {
            float4 A0 = *(const float4*)&As[k * 128 + ty * 8];
            float4 A1 = *(const float4*)&As[k * 128 + ty * 8 + 4];
            ulonglong2 B0 = *(const ulonglong2*)&Bs[k * 128 + tx * 8];
            ulonglong2 B1 = *(const ulonglong2*)&Bs[k * 128 + tx * 8 + 4];
            float a[8] = {A0.x, A0.y, A0.z, A0.w, A1.x, A1.y, A1.z, A1.w};
#pragma unroll
            for (int i = 0; i < 8; i++) {
                unsigned long long av = pack2(a[i]);
                fma2(acc[i][0], av, B0.x);
                fma2(acc[i][1], av, B0.y);
                fma2(acc[i][2], av, B1.x);
                fma2(acc[i][3], av, B1.y);
            }
        }

        // fold chunk scores into running argmin
#pragma unroll
        for (int i = 0; i < 8; i++) {
#pragma unroll
            for (int j2 = 0; j2 < 4; j2++) {
                float lo, hi;
                unpack2(acc[i][j2], lo, hi);
                int n0 = cbBase + tx * 8 + j2 * 2;
                float sc0 = c2s[n0] - 2.f * lo;
                float sc1 = c2s[n0 + 1] - 2.f * hi;
                if (sc0 < best[i] || (sc0 == best[i] && n0 < bidx[i])) { best[i] = sc0; bidx[i] = n0; }
                if (sc1 < best[i] || (sc1 == best[i] && (n0 + 1) < bidx[i])) { best[i] = sc1; bidx[i] = n0 + 1; }
            }
        }
    }

    // reduce argmin across the 16 tx lanes (width-16 shfl, first-min tie-break)
#pragma unroll
    for (int off = 8; off >= 1; off >>= 1) {
#pragma unroll
        for (int i = 0; i < 8; i++) {
            float ob = __shfl_down_sync(0xffffffffu, best[i], off, 16);
            int   oi = __shfl_down_sync(0xffffffffu, bidx[i], off, 16);
            if (ob < best[i] || (ob == best[i] && oi < bidx[i])) { best[i] = ob; bidx[i] = oi; }
        }
    }
    if (tx == 0) {
#pragma unroll
        for (int i = 0; i < 8; i++) {
            int s = segBase + ty * 8 + i;
            if (s < segTotal) g_idx[s] = bidx[i];
        }
    }
}

// ============================================================
// K3: scatter quantized codewords, idx_out, e_latent partials
// ============================================================
__global__ void k3_scatter(const float4* __restrict__ cb4,
                           float4* __restrict__ q4,
                           float*  __restrict__ idx_out)
{
    __shared__ float red[256];
    int tid = threadIdx.x;
    int s_local = tid >> 3;
    int g = tid & 7;
    int s = blockIdx.x * 32 + s_local;

    int ci = g_idx[s];
    const float4* pooled4 = (const float4*)g_pooled;

    float4 c[6];
    float ssum = 0.f;
#pragma unroll
    for (int i = 0; i < 6; i++) {
        c[i] = __ldg(&cb4[(size_t)ci * DIM4 + g + 8 * i]);
        float4 p = pooled4[(size_t)s * DIM4 + g + 8 * i];
        float dx = c[i].x - p.x, dy = c[i].y - p.y, dz = c[i].z - p.z, dw = c[i].w - p.w;
        ssum += dx * dx + dy * dy + dz * dz + dw * dw;
    }

    int tokBase = s * SPAN;
#pragma unroll
    for (int j = 0; j < SPAN; j++) {
        float4* dst = q4 + (size_t)(tokBase + j) * DIM4;
#pragma unroll
        for (int i = 0; i < 6; i++)
            dst[g + 8 * i] = c[i];
    }
    idx_out[tokBase + g] = (float)ci;

    red[tid] = ssum;
    __syncthreads();
#pragma unroll
    for (int st = 128; st > 0; st >>= 1) {
        if (tid < st) red[tid] += red[tid + st];
        __syncthreads();
    }
    if (tid == 0) g_partial[blockIdx.x] = red[0];
}

// ============================================================
// K4: finalize scalar loss (ordered, deterministic)
// ============================================================
__global__ void k4_final(int nPartial, long nsD, long nTok, float* __restrict__ loss_out)
{
    if (threadIdx.x == 0 && blockIdx.x == 0) {
        double s = 0.0;
        for (int i = 0; i < nPartial; i++) s += (double)g_partial[i];
        double e_latent = s / (double)nsD;
        double bmean = (double)g_count / (double)nTok;
        double d = bmean - 0.125;
        *loss_out = (float)(0.25 * e_latent + 0.01 * d * d);
    }
}

// ============================================================
// launch
// inputs: x [B,T,D] f32, codebook [K,D] f32, boundary_w [D] f32, boundary_b [1] f32
// output (f32 concat): q_out [B*T*D] | total_loss [1] | idx_out [B*T] | boundaries [B*T]
// ============================================================
extern "C" void kernel_launch(void* const* d_in, const int* in_sizes, int n_in,
                              void* d_out, int out_size)
{
    const float* x   = (const float*)d_in[0];
    const float* cbk = (const float*)d_in[1];
    const float* bw  = (const float*)d_in[2];
    const float* bb  = (const float*)d_in[3];

    int  Dd   = in_sizes[2];                 // 192
    int  K    = in_sizes[1] / Dd;            // 512
    long nTok = (long)in_sizes[0] / Dd;      // 131072
    long NS   = nTok / SPAN;                 // 16384

    float* q_out    = (float*)d_out;
    float* loss_out = q_out + nTok * (long)Dd;
    float* idx_out  = loss_out + 1;
    float* bnd_out  = idx_out + nTok;

    const int smem2 = (192 * 128 * 2 + KCB) * (int)sizeof(float);  // 198,656 B
    cudaFuncSetAttribute(k2_vq, cudaFuncAttributeMaxDynamicSharedMemorySize, smem2);

    k0_c2<<<(K + 255) / 256, 256>>>(cbk, K);
    k1_pool_boundary<<<(int)(NS / 32), 256>>>((const float4*)x, (const float4*)bw, bb, bnd_out);
    k2_vq<<<(int)(NS / 128), 256, smem2>>>((const float4*)cbk, (int)NS);
    k3_scatter<<<(int)(NS / 32), 256>>>((const float4*)cbk, (float4*)q_out, idx_out);
    k4_final<<<1, 32>>>((int)(NS / 32), NS * (long)Dd, nTok, loss_out);
}

// round 4
// speedup vs baseline: 1.4438x; 1.1800x over previous
#include <cuda_runtime.h>
#include <stdint.h>

// Problem constants
#define SPAN   8
#define DIM    192
#define DIM4   48          // DIM / 4
#define KCB    512
#define MAX_NS 16384       // B*T/SPAN
#define MAX_N  131072      // B*T

// -------- device scratch (no allocations allowed) --------
__device__ float        g_pooled[MAX_NS * DIM];   // 12.6 MB
__device__ float        g_c2[KCB];
__device__ float        g_partial[512];
__device__ unsigned int g_count;

// ---- packed fp32x2 helpers (Blackwell FFMA2 path) ----
__device__ __forceinline__ unsigned long long pack2(float x) {
    unsigned long long r;
    asm("mov.b64 %0, {%1, %1};" : "=l"(r) : "f"(x));
    return r;
}
__device__ __forceinline__ void fma2(unsigned long long& d,
                                     unsigned long long a, unsigned long long b) {
    asm("fma.rn.f32x2 %0, %1, %2, %0;" : "+l"(d) : "l"(a), "l"(b));
}
__device__ __forceinline__ void unpack2(unsigned long long v, float& lo, float& hi) {
    asm("mov.b64 {%0, %1}, %2;" : "=f"(lo), "=f"(hi) : "l"(v));
}

// ============================================================
// K0: codebook squared norms + reset boundary counter
// ============================================================
__global__ void k0_c2(const float* __restrict__ codebook, int K)
{
    int k = blockIdx.x * blockDim.x + threadIdx.x;
    if (k == 0) g_count = 0u;
    if (k < K) {
        const float4* row = (const float4*)(codebook + (size_t)k * DIM);
        float s = 0.f;
#pragma unroll
        for (int i = 0; i < DIM4; i++) {
            float4 v = row[i];
            s += v.x * v.x + v.y * v.y + v.z * v.z + v.w * v.w;
        }
        g_c2[k] = s;
    }
}

// ============================================================
// K1: single pass over x -> pooled, boundaries, boundary count
// Block: 128 threads = 16 segments x 8 lane-groups (1024 blocks -> high occ).
// ============================================================
__global__ void __launch_bounds__(128) k1_pool_boundary(
    const float4* __restrict__ x4,
    const float4* __restrict__ w4,
    const float*  __restrict__ bbias,
    float* __restrict__ bnd_out)
{
    int tid = threadIdx.x;
    int s_local = tid >> 3;
    int g = tid & 7;
    int s = blockIdx.x * 16 + s_local;

    float4 wv[6];
#pragma unroll
    for (int i = 0; i < 6; i++) wv[i] = __ldg(&w4[g + 8 * i]);

    float4 pool[6];
#pragma unroll
    for (int i = 0; i < 6; i++) pool[i] = make_float4(0.f, 0.f, 0.f, 0.f);

    float part[SPAN];
    int tokBase = s * SPAN;

#pragma unroll
    for (int j = 0; j < SPAN; j++) {
        const float4* row = x4 + (size_t)(tokBase + j) * DIM4;
        float pj = 0.f;
#pragma unroll
        for (int i = 0; i < 6; i++) {
            float4 v = __ldcs(&row[g + 8 * i]);   // streaming: x is single-use
            pool[i].x += v.x; pool[i].y += v.y; pool[i].z += v.z; pool[i].w += v.w;
            pj += v.x * wv[i].x + v.y * wv[i].y + v.z * wv[i].z + v.w * wv[i].w;
        }
        part[j] = pj;
    }

    float4* pooled4 = (float4*)g_pooled;
#pragma unroll
    for (int i = 0; i < 6; i++) {
        float4 p = pool[i];
        p.x *= 0.125f; p.y *= 0.125f; p.z *= 0.125f; p.w *= 0.125f;
        pooled4[(size_t)s * DIM4 + g + 8 * i] = p;
    }

#pragma unroll
    for (int m = 1; m < 8; m <<= 1) {
#pragma unroll
        for (int j = 0; j < SPAN; j++)
            part[j] += __shfl_xor_sync(0xffffffffu, part[j], m);
    }

    float bb = __ldg(bbias);
    float logit = part[g] + bb;
    float b = (logit > 0.f) ? 1.f : 0.f;
    bnd_out[tokBase + g] = b;

    unsigned bal = __ballot_sync(0xffffffffu, b > 0.f);
    if ((tid & 31) == 0) atomicAdd(&g_count, (unsigned)__popc(bal));
}

// ============================================================
// K2 v3: VQ distance GEMM + fused argmin + FUSED scatter epilogue
//   GEMM core identical to v2 (128 segs x 512 codes, FFMA2, 8x8 tile).
//   Epilogue: block scatters its 128 segments' codewords to q_out
//   (streaming stores), writes idx_out, accumulates e_latent partial.
// ============================================================
__global__ void __launch_bounds__(256, 1) k2_vq_fused(
    const float4* __restrict__ cb4,
    float4* __restrict__ q4,
    float*  __restrict__ idx_out)
{
    extern __shared__ float smem[];
    float* As  = smem;                 // 192*128
    float* Bs  = As + 192 * 128;       // 192*128
    float* c2s = Bs + 192 * 128;       // 512

    int tid = threadIdx.x;
    int ty = tid >> 4;
    int tx = tid & 15;
    int segBase = blockIdx.x * 128;

    for (int i = tid; i < KCB; i += 256) c2s[i] = g_c2[i];

    // ---- load pooled tile, transpose to k-major As[k][m] ----
    {
        const float4* p4 = (const float4*)g_pooled;
        for (int it = 0; it < 6; it++) {
            int item = tid + it * 256;
            int m_grp = item & 31;
            int kq = item >> 5;
            float4 v0 = p4[(size_t)(segBase + m_grp * 4 + 0) * DIM4 + kq];
            float4 v1 = p4[(size_t)(segBase + m_grp * 4 + 1) * DIM4 + kq];
            float4 v2 = p4[(size_t)(segBase + m_grp * 4 + 2) * DIM4 + kq];
            float4 v3 = p4[(size_t)(segBase + m_grp * 4 + 3) * DIM4 + kq];
            const float* a0 = (const float*)&v0;
            const float* a1 = (const float*)&v1;
            const float* a2 = (const float*)&v2;
            const float* a3 = (const float*)&v3;
#pragma unroll
            for (int u = 0; u < 4; u++) {
                *(float4*)&As[(kq * 4 + u) * 128 + m_grp * 4] =
                    make_float4(a0[u], a1[u], a2[u], a3[u]);
            }
        }
    }

    float best[8];
    int   bidx[8];
#pragma unroll
    for (int i = 0; i < 8; i++) { best[i] = 3.4e38f; bidx[i] = 0; }

    for (int nc = 0; nc < 4; nc++) {
        __syncthreads();

        int cbBase = nc * 128;
        for (int it = 0; it < 6; it++) {
            int item = tid + it * 256;
            int n_grp = item & 31;
            int kq = item >> 5;
            float4 v0 = cb4[(size_t)(cbBase + n_grp * 4 + 0) * DIM4 + kq];
            float4 v1 = cb4[(size_t)(cbBase + n_grp * 4 + 1) * DIM4 + kq];
            float4 v2 = cb4[(size_t)(cbBase + n_grp * 4 + 2) * DIM4 + kq];
            float4 v3 = cb4[(size_t)(cbBase + n_grp * 4 + 3) * DIM4 + kq];
            const float* b0 = (const float*)&v0;
            const float* b1 = (const float*)&v1;
            const float* b2 = (const float*)&v2;
            const float* b3 = (const float*)&v3;
#pragma unroll
            for (int u = 0; u < 4; u++) {
                *(float4*)&Bs[(kq * 4 + u) * 128 + n_grp * 4] =
                    make_float4(b0[u], b1[u], b2[u], b3[u]);
            }
        }
        __syncthreads();

        unsigned long long acc[8][4];
#pragma unroll
        for (int i = 0; i < 8; i++)
#pragma unroll
            for (int j = 0; j < 4; j++) acc[i][j] = 0ull;

#pragma unroll 4
        for (int k = 0; k < DIM; k++) {
            float4 A0 = *(const float4*)&As[k * 128 + ty * 8];
            float4 A1 = *(const float4*)&As[k * 128 + ty * 8 + 4];
            ulonglong2 B0 = *(const ulonglong2*)&Bs[k * 128 + tx * 8];
            ulonglong2 B1 = *(const ulonglong2*)&Bs[k * 128 + tx * 8 + 4];
            float a[8] = {A0.x, A0.y, A0.z, A0.w, A1.x, A1.y, A1.z, A1.w};
#pragma unroll
            for (int i = 0; i < 8; i++) {
                unsigned long long av = pack2(a[i]);
                fma2(acc[i][0], av, B0.x);
                fma2(acc[i][1], av, B0.y);
                fma2(acc[i][2], av, B1.x);
                fma2(acc[i][3], av, B1.y);
            }
        }

#pragma unroll
        for (int i = 0; i < 8; i++) {
#pragma unroll
            for (int j2 = 0; j2 < 4; j2++) {
                float lo, hi;
                unpack2(acc[i][j2], lo, hi);
                int n0 = cbBase + tx * 8 + j2 * 2;
                float sc0 = c2s[n0] - 2.f * lo;
                float sc1 = c2s[n0 + 1] - 2.f * hi;
                if (sc0 < best[i] || (sc0 == best[i] && n0 < bidx[i])) { best[i] = sc0; bidx[i] = n0; }
                if (sc1 < best[i] || (sc1 == best[i] && (n0 + 1) < bidx[i])) { best[i] = sc1; bidx[i] = n0 + 1; }
            }
        }
    }

    // reduce argmin across the 16 tx lanes (width-16 shfl, first-min tie-break)
#pragma unroll
    for (int off = 8; off >= 1; off >>= 1) {
#pragma unroll
        for (int i = 0; i < 8; i++) {
            float ob = __shfl_down_sync(0xffffffffu, best[i], off, 16);
            int   oi = __shfl_down_sync(0xffffffffu, bidx[i], off, 16);
            if (ob < best[i] || (ob == best[i] && oi < bidx[i])) { best[i] = ob; bidx[i] = oi; }
        }
    }

    // ---- fused scatter epilogue ----
    __syncthreads();                 // GEMM smem reads done; safe to repurpose
    int*   sidx = (int*)smem;        // [128]
    float* red  = smem + 256;        // [256]

    if (tx == 0) {
#pragma unroll
        for (int i = 0; i < 8; i++) sidx[ty * 8 + i] = bidx[i];
    }
    __syncthreads();

    // 4 passes x (32 segs x 8 lane-groups), same mapping as old k3
    int s_local = tid >> 3;
    int g = tid & 7;
    const float4* pooled4 = (const float4*)g_pooled;
    float ssum = 0.f;

#pragma unroll
    for (int p = 0; p < 4; p++) {
        int sl = p * 32 + s_local;
        int s  = segBase + sl;
        int ci = sidx[sl];

        float4 c[6];
#pragma unroll
        for (int i = 0; i < 6; i++) {
            c[i] = __ldg(&cb4[(size_t)ci * DIM4 + g + 8 * i]);
            float4 pv = __ldg(&pooled4[(size_t)s * DIM4 + g + 8 * i]);
            float dx = c[i].x - pv.x, dy = c[i].y - pv.y,
                  dz = c[i].z - pv.z, dw = c[i].w - pv.w;
            ssum += dx * dx + dy * dy + dz * dz + dw * dw;
        }

        int tokBase = s * SPAN;
#pragma unroll
        for (int j = 0; j < SPAN; j++) {
            float4* dst = q4 + (size_t)(tokBase + j) * DIM4;
#pragma unroll
            for (int i = 0; i < 6; i++)
                __stcs(&dst[g + 8 * i], c[i]);    // streaming store
        }
        idx_out[tokBase + g] = (float)ci;
    }

    red[tid] = ssum;
    __syncthreads();
#pragma unroll
    for (int st = 128; st > 0; st >>= 1) {
        if (tid < st) red[tid] += red[tid + st];
        __syncthreads();
    }
    if (tid == 0) g_partial[blockIdx.x] = red[0];
}

// ============================================================
// K4: finalize scalar loss (ordered, deterministic)
// ============================================================
__global__ void k4_final(int nPartial, long nsD, long nTok, float* __restrict__ loss_out)
{
    if (threadIdx.x == 0 && blockIdx.x == 0) {
        double s = 0.0;
        for (int i = 0; i < nPartial; i++) s += (double)g_partial[i];
        double e_latent = s / (double)nsD;
        double bmean = (double)g_count / (double)nTok;
        double d = bmean - 0.125;
        *loss_out = (float)(0.25 * e_latent + 0.01 * d * d);
    }
}

// ============================================================
// launch
// inputs: x [B,T,D] f32, codebook [K,D] f32, boundary_w [D] f32, boundary_b [1] f32
// output (f32 concat): q_out [B*T*D] | total_loss [1] | idx_out [B*T] | boundaries [B*T]
// ============================================================
extern "C" void kernel_launch(void* const* d_in, const int* in_sizes, int n_in,
                              void* d_out, int out_size)
{
    const float* x   = (const float*)d_in[0];
    const float* cbk = (const float*)d_in[1];
    const float* bw  = (const float*)d_in[2];
    const float* bb  = (const float*)d_in[3];

    int  Dd   = in_sizes[2];                 // 192
    int  K    = in_sizes[1] / Dd;            // 512
    long nTok = (long)in_sizes[0] / Dd;      // 131072
    long NS   = nTok / SPAN;                 // 16384

    float* q_out    = (float*)d_out;
    float* loss_out = q_out + nTok * (long)Dd;
    float* idx_out  = loss_out + 1;
    float* bnd_out  = idx_out + nTok;

    const int smem2 = (192 * 128 * 2 + KCB) * (int)sizeof(float);  // 198,656 B
    cudaFuncSetAttribute(k2_vq_fused, cudaFuncAttributeMaxDynamicSharedMemorySize, smem2);

    int nBlocks2 = (int)(NS / 128);          // 128

    k0_c2<<<(K + 255) / 256, 256>>>(cbk, K);
    k1_pool_boundary<<<(int)(NS / 16), 128>>>((const float4*)x, (const float4*)bw, bb, bnd_out);
    k2_vq_fused<<<nBlocks2, 256, smem2>>>((const float4*)cbk, (float4*)q_out, idx_out);
    k4_final<<<1, 32>>>(nBlocks2, NS * (long)Dd, nTok, loss_out);
}

// round 7
// speedup vs baseline: 1.7883x; 1.2386x over previous
#include <cuda_runtime.h>
#include <cuda_bf16.h>
#include <stdint.h>

#define SPAN   8
#define DIM    192
#define DIM4   48
#define KCB    512
#define MAX_NS 16384
#define BAND   5e-5f
#define LDS    200            // bf16 elements per smem row (400 B, conflict-free ldmatrix)

// smem layout (bytes)
#define OFF_AHI  0
#define OFF_ALO  51200
#define OFF_BHI  102400
#define OFF_BLO  153600
#define OFF_C2   204800
#define OFF_SIDX 206848
#define OFF_RED  207360
#define SM_TOTAL 208384

// -------- device scratch --------
__device__ float        g_pooled[MAX_NS * DIM];
__device__ float        g_c2[KCB];
__device__ float        g_partial[128];
__device__ unsigned int g_count;

// ============ helpers ============
__device__ __forceinline__ uint32_t smem_u32(const void* p) {
    uint32_t a;
    asm("{ .reg .u64 t; cvta.to.shared.u64 t, %1; cvt.u32.u64 %0, t; }" : "=r"(a) : "l"(p));
    return a;
}
__device__ __forceinline__ void ldsm_x4(uint32_t& r0, uint32_t& r1, uint32_t& r2, uint32_t& r3,
                                        uint32_t addr) {
    asm volatile("ldmatrix.sync.aligned.m8n8.x4.shared.b16 {%0,%1,%2,%3}, [%4];"
        : "=r"(r0), "=r"(r1), "=r"(r2), "=r"(r3) : "r"(addr));
}
__device__ __forceinline__ void ldsm_x2(uint32_t& r0, uint32_t& r1, uint32_t addr) {
    asm volatile("ldmatrix.sync.aligned.m8n8.x2.shared.b16 {%0,%1}, [%2];"
        : "=r"(r0), "=r"(r1) : "r"(addr));
}
__device__ __forceinline__ void mma16816(float& d0, float& d1, float& d2, float& d3,
                                         uint32_t a0, uint32_t a1, uint32_t a2, uint32_t a3,
                                         uint32_t b0, uint32_t b1) {
    asm volatile("mma.sync.aligned.m16n8k16.row.col.f32.bf16.bf16.f32 "
        "{%0,%1,%2,%3}, {%4,%5,%6,%7}, {%8,%9}, {%0,%1,%2,%3};"
        : "+f"(d0), "+f"(d1), "+f"(d2), "+f"(d3)
        : "r"(a0), "r"(a1), "r"(a2), "r"(a3), "r"(b0), "r"(b1));
}

// top-4 insertion (strict <  -> earlier/lower index kept on equal)
__device__ __forceinline__ void ins4(float* s, int* id, float sc, int n) {
    if (sc < s[3]) {
        if (sc < s[0])      { s[3]=s[2];id[3]=id[2]; s[2]=s[1];id[2]=id[1]; s[1]=s[0];id[1]=id[0]; s[0]=sc;id[0]=n; }
        else if (sc < s[1]) { s[3]=s[2];id[3]=id[2]; s[2]=s[1];id[2]=id[1]; s[1]=sc;id[1]=n; }
        else if (sc < s[2]) { s[3]=s[2];id[3]=id[2]; s[2]=sc;id[2]=n; }
        else                { s[3]=sc;id[3]=n; }
    }
}

__device__ __forceinline__ float dot192(const float* a, const float* b) {
    const float4* a4 = (const float4*)a;
    const float4* b4 = (const float4*)b;
    float s = 0.f;
#pragma unroll
    for (int i = 0; i < 48; i++) {
        float4 x = a4[i], y = b4[i];
        s += x.x * y.x + x.y * y.y + x.z * y.z + x.w * y.w;
    }
    return s;
}
__device__ __forceinline__ int exact_argmin(const float* prow, const float* cbk,
                                            const float* c2s) {
    float best = 3.4e38f; int bi = 0;
    for (int n = 0; n < KCB; n++) {
        float sc = c2s[n] - 2.f * dot192(prow, cbk + (size_t)n * DIM);
        if (sc < best) { best = sc; bi = n; }
    }
    return bi;
}

// resolve argmin from approx top-4 with band guard (exact fp32 semantics)
__device__ __forceinline__ int resolve_idx(const float* tS, const int* tI, int segRow,
                                           const float* cbk, const float* c2s) {
    int idx = tI[0];
    if (tS[1] - tS[0] <= BAND) {
        const float* prow = g_pooled + (size_t)segRow * DIM;
        if (tS[3] - tS[0] <= BAND) {
            idx = exact_argmin(prow, cbk, c2s);
        } else {
            int cand[4]; int nc = 0;
            cand[nc++] = tI[0];
            cand[nc++] = tI[1];
            if (tS[2] - tS[0] <= BAND) cand[nc++] = tI[2];
            for (int a = 0; a < nc; a++)
                for (int b = a + 1; b < nc; b++)
                    if (cand[b] < cand[a]) { int t = cand[a]; cand[a] = cand[b]; cand[b] = t; }
            float best = 3.4e38f; int bi = 0;
            for (int a = 0; a < nc; a++) {
                int n = cand[a];
                float sc = c2s[n] - 2.f * dot192(prow, cbk + (size_t)n * DIM);
                if (sc < best) { best = sc; bi = n; }
            }
            idx = bi;
        }
    }
    return idx;
}

// ============================================================
// K0: codebook squared norms + reset boundary counter
// ============================================================
__global__ void k0_c2(const float* __restrict__ codebook, int K)
{
    int k = blockIdx.x * blockDim.x + threadIdx.x;
    if (k == 0) g_count = 0u;
    if (k < K) {
        const float4* row = (const float4*)(codebook + (size_t)k * DIM);
        float s = 0.f;
#pragma unroll
        for (int i = 0; i < DIM4; i++) {
            float4 v = row[i];
            s += v.x * v.x + v.y * v.y + v.z * v.z + v.w * v.w;
        }
        g_c2[k] = s;
    }
}

// ============================================================
// K1: pooled + boundaries (proven)
// ============================================================
__global__ void __launch_bounds__(128) k1_pool_boundary(
    const float4* __restrict__ x4, const float4* __restrict__ w4,
    const float* __restrict__ bbias, float* __restrict__ bnd_out)
{
    int tid = threadIdx.x;
    int s_local = tid >> 3;
    int g = tid & 7;
    int s = blockIdx.x * 16 + s_local;

    float4 wv[6];
#pragma unroll
    for (int i = 0; i < 6; i++) wv[i] = __ldg(&w4[g + 8 * i]);
    float4 pool[6];
#pragma unroll
    for (int i = 0; i < 6; i++) pool[i] = make_float4(0.f, 0.f, 0.f, 0.f);

    float part[SPAN];
    int tokBase = s * SPAN;
#pragma unroll
    for (int j = 0; j < SPAN; j++) {
        const float4* row = x4 + (size_t)(tokBase + j) * DIM4;
        float pj = 0.f;
#pragma unroll
        for (int i = 0; i < 6; i++) {
            float4 v = __ldcs(&row[g + 8 * i]);
            pool[i].x += v.x; pool[i].y += v.y; pool[i].z += v.z; pool[i].w += v.w;
            pj += v.x * wv[i].x + v.y * wv[i].y + v.z * wv[i].z + v.w * wv[i].w;
        }
        part[j] = pj;
    }
    float4* pooled4 = (float4*)g_pooled;
#pragma unroll
    for (int i = 0; i < 6; i++) {
        float4 p = pool[i];
        p.x *= 0.125f; p.y *= 0.125f; p.z *= 0.125f; p.w *= 0.125f;
        pooled4[(size_t)s * DIM4 + g + 8 * i] = p;
    }
#pragma unroll
    for (int m = 1; m < 8; m <<= 1) {
#pragma unroll
        for (int j = 0; j < SPAN; j++)
            part[j] += __shfl_xor_sync(0xffffffffu, part[j], m);
    }
    float bb = __ldg(bbias);
    float b = (part[g] + bb > 0.f) ? 1.f : 0.f;
    bnd_out[tokBase + g] = b;
    unsigned bal = __ballot_sync(0xffffffffu, b > 0.f);
    if ((tid & 31) == 0) atomicAdd(&g_count, (unsigned)__popc(bal));
}

// ============================================================
// K2 v5: mma.sync bf16 split-precision VQ + guarded argmin + fused scatter
//   128 segs/block, 8 warps x 16 rows. A (pooled hi/lo) resident in smem,
//   B (codes hi/lo) streamed in 4 chunks of 128. 3-term HMMA (hh+lh+hl),
//   fp32 accum. Top-4 + band guard -> exact fp32 rescore.
// ============================================================
__global__ void __launch_bounds__(256, 1) k2_vq_mma(
    const float* __restrict__ cbk,
    float4* __restrict__ q4,
    float*  __restrict__ idx_out)
{
    extern __shared__ char smem[];
    uint32_t sb = smem_u32(smem);
    int tid  = threadIdx.x;
    int warp = tid >> 5;
    int lane = tid & 31;
    int segBase = blockIdx.x * 128;

    float* c2s  = (float*)(smem + OFF_C2);
    int*   sidx = (int*)(smem + OFF_SIDX);
    float* red  = (float*)(smem + OFF_RED);

    // ---- stage A (pooled -> bf16 hi/lo, row-major stride LDS) ----
    {
        const float2* p2 = (const float2*)g_pooled;
#pragma unroll
        for (int it = 0; it < 48; it++) {
            int item = tid + it * 256;
            int row = item / 96;
            int cp  = item - row * 96;
            float2 v = p2[(size_t)(segBase + row) * 96 + cp];
            __nv_bfloat16 h0 = __float2bfloat16(v.x);
            __nv_bfloat16 h1 = __float2bfloat16(v.y);
            __nv_bfloat16 l0 = __float2bfloat16(v.x - __bfloat162float(h0));
            __nv_bfloat16 l1 = __float2bfloat16(v.y - __bfloat162float(h1));
            int off = (row * LDS + cp * 2) * 2;
            *(__nv_bfloat162*)(smem + OFF_AHI + off) = __nv_bfloat162(h0, h1);
            *(__nv_bfloat162*)(smem + OFF_ALO + off) = __nv_bfloat162(l0, l1);
        }
    }
    for (int i = tid; i < KCB; i += 256) c2s[i] = g_c2[i];

    // per-thread top-4 for two rows (r0 = warp*16 + lane/4, r1 = r0 + 8)
    float tS0[4], tS1[4]; int tI0[4], tI1[4];
#pragma unroll
    for (int j = 0; j < 4; j++) { tS0[j] = 3.4e38f; tS1[j] = 3.4e38f; tI0[j] = 0; tI1[j] = 0; }

    // ldmatrix lane address components
    int arow = warp * 16 + (lane & 15);
    int acol = (lane >> 4) << 3;
    int brow = lane & 7;
    int bcol = ((lane >> 3) & 1) << 3;
    uint32_t aAddrH = sb + OFF_AHI + (uint32_t)(arow * LDS + acol) * 2;
    uint32_t aAddrL = sb + OFF_ALO + (uint32_t)(arow * LDS + acol) * 2;

    for (int chunk = 0; chunk < 4; chunk++) {
        if (chunk) __syncthreads();          // previous chunk's B reads done

        // ---- stage B chunk (128 codes -> bf16 hi/lo) ----
        {
            const float2* cb2 = (const float2*)cbk;
            int rowBase = chunk * 128;
#pragma unroll
            for (int it = 0; it < 48; it++) {
                int item = tid + it * 256;
                int row = item / 96;
                int cp  = item - row * 96;
                float2 v = __ldg(&cb2[(size_t)(rowBase + row) * 96 + cp]);
                __nv_bfloat16 h0 = __float2bfloat16(v.x);
                __nv_bfloat16 h1 = __float2bfloat16(v.y);
                __nv_bfloat16 l0 = __float2bfloat16(v.x - __bfloat162float(h0));
                __nv_bfloat16 l1 = __float2bfloat16(v.y - __bfloat162float(h1));
                int off = (row * LDS + cp * 2) * 2;
                *(__nv_bfloat162*)(smem + OFF_BHI + off) = __nv_bfloat162(h0, h1);
                *(__nv_bfloat162*)(smem + OFF_BLO + off) = __nv_bfloat162(l0, l1);
            }
        }
        __syncthreads();

        float acc[16][4];
#pragma unroll
        for (int nt = 0; nt < 16; nt++)
#pragma unroll
            for (int j = 0; j < 4; j++) acc[nt][j] = 0.f;

        for (int kt = 0; kt < 12; kt++) {
            uint32_t kb = (uint32_t)(kt * 16) * 2;
            uint32_t ah0, ah1, ah2, ah3, al0, al1, al2, al3;
            ldsm_x4(ah0, ah1, ah2, ah3, aAddrH + kb);
            ldsm_x4(al0, al1, al2, al3, aAddrL + kb);
#pragma unroll
            for (int nt = 0; nt < 16; nt++) {
                uint32_t bAddr = sb + OFF_BHI + (uint32_t)((nt * 8 + brow) * LDS + kt * 16 + bcol) * 2;
                uint32_t bh0, bh1, bl0, bl1;
                ldsm_x2(bh0, bh1, bAddr);
                ldsm_x2(bl0, bl1, bAddr + (OFF_BLO - OFF_BHI));
                mma16816(acc[nt][0], acc[nt][1], acc[nt][2], acc[nt][3], ah0, ah1, ah2, ah3, bh0, bh1);
                mma16816(acc[nt][0], acc[nt][1], acc[nt][2], acc[nt][3], al0, al1, al2, al3, bh0, bh1);
                mma16816(acc[nt][0], acc[nt][1], acc[nt][2], acc[nt][3], ah0, ah1, ah2, ah3, bl0, bl1);
            }
        }

        // fold into top-4 (D frag: d0/d1 row lane/4, d2/d3 row lane/4+8; cols 2*(lane&3)+{0,1})
#pragma unroll
        for (int nt = 0; nt < 16; nt++) {
            int n0 = chunk * 128 + nt * 8 + 2 * (lane & 3);
            float cA = c2s[n0], cB = c2s[n0 + 1];
            ins4(tS0, tI0, cA - 2.f * acc[nt][0], n0);
            ins4(tS0, tI0, cB - 2.f * acc[nt][1], n0 + 1);
            ins4(tS1, tI1, cA - 2.f * acc[nt][2], n0);
            ins4(tS1, tI1, cB - 2.f * acc[nt][3], n0 + 1);
        }
    }

    // ---- merge top-4 across the 4 lanes of each quad (butterfly) ----
#pragma unroll
    for (int m = 1; m <= 2; m <<= 1) {
        float os[4]; int oi[4];
#pragma unroll
        for (int j = 0; j < 4; j++) {
            os[j] = __shfl_xor_sync(0xffffffffu, tS0[j], m);
            oi[j] = __shfl_xor_sync(0xffffffffu, tI0[j], m);
        }
#pragma unroll
        for (int j = 0; j < 4; j++) ins4(tS0, tI0, os[j], oi[j]);
#pragma unroll
        for (int j = 0; j < 4; j++) {
            os[j] = __shfl_xor_sync(0xffffffffu, tS1[j], m);
            oi[j] = __shfl_xor_sync(0xffffffffu, tI1[j], m);
        }
#pragma unroll
        for (int j = 0; j < 4; j++) ins4(tS1, tI1, os[j], oi[j]);
    }

    // ---- guard + write indices (one lane per quad, two rows each) ----
    if ((lane & 3) == 0) {
        int r0 = warp * 16 + (lane >> 2);
        int r1 = r0 + 8;
        sidx[r0] = resolve_idx(tS0, tI0, segBase + r0, cbk, c2s);
        sidx[r1] = resolve_idx(tS1, tI1, segBase + r1, cbk, c2s);
    }
    __syncthreads();

    // ---- fused scatter (proven code path) ----
    {
        int s_local = tid >> 3;
        int g = tid & 7;
        const float4* pooled4 = (const float4*)g_pooled;
        const float4* cb4 = (const float4*)cbk;
        float ssum = 0.f;
#pragma unroll
        for (int p = 0; p < 4; p++) {
            int sl = p * 32 + s_local;
            int s  = segBase + sl;
            int ci = sidx[sl];
            float4 c[6];
#pragma unroll
            for (int i = 0; i < 6; i++) {
                c[i] = __ldg(&cb4[(size_t)ci * DIM4 + g + 8 * i]);
                float4 pv = __ldg(&pooled4[(size_t)s * DIM4 + g + 8 * i]);
                float dx = c[i].x - pv.x, dy = c[i].y - pv.y,
                      dz = c[i].z - pv.z, dw = c[i].w - pv.w;
                ssum += dx * dx + dy * dy + dz * dz + dw * dw;
            }
            int tokBase = s * SPAN;
#pragma unroll
            for (int j = 0; j < SPAN; j++) {
                float4* dst = q4 + (size_t)(tokBase + j) * DIM4;
#pragma unroll
                for (int i = 0; i < 6; i++)
                    __stcs(&dst[g + 8 * i], c[i]);
            }
            idx_out[tokBase + g] = (float)ci;
        }
        red[tid] = ssum;
    }
    __syncthreads();
#pragma unroll
    for (int st = 128; st > 0; st >>= 1) {
        if (tid < st) red[tid] += red[tid + st];
        __syncthreads();
    }
    if (tid == 0) g_partial[blockIdx.x] = red[0];
}

// ============================================================
// K4: finalize scalar loss (parallel deterministic tree)
// ============================================================
__global__ void k4_final(long nsD, long nTok, float* __restrict__ loss_out)
{
    __shared__ double sd[128];
    int t = threadIdx.x;
    sd[t] = (double)g_partial[t];
    __syncthreads();
#pragma unroll
    for (int st = 64; st > 0; st >>= 1) {
        if (t < st) sd[t] += sd[t + st];
        __syncthreads();
    }
    if (t == 0) {
        double e_latent = sd[0] / (double)nsD;
        double bmean = (double)g_count / (double)nTok;
        double d = bmean - 0.125;
        *loss_out = (float)(0.25 * e_latent + 0.01 * d * d);
    }
}

// ============================================================
// launch
// inputs: x [B,T,D] f32, codebook [K,D] f32, boundary_w [D] f32, boundary_b [1] f32
// output (f32 concat): q_out | total_loss | idx_out | boundaries
// ============================================================
extern "C" void kernel_launch(void* const* d_in, const int* in_sizes, int n_in,
                              void* d_out, int out_size)
{
    const float* x   = (const float*)d_in[0];
    const float* cbk = (const float*)d_in[1];
    const float* bw  = (const float*)d_in[2];
    const float* bb  = (const float*)d_in[3];

    int  Dd   = in_sizes[2];                 // 192
    int  K    = in_sizes[1] / Dd;            // 512
    long nTok = (long)in_sizes[0] / Dd;      // 131072
    long NS   = nTok / SPAN;                 // 16384

    float* q_out    = (float*)d_out;
    float* loss_out = q_out + nTok * (long)Dd;
    float* idx_out  = loss_out + 1;
    float* bnd_out  = idx_out + nTok;

    cudaFuncSetAttribute(k2_vq_mma, cudaFuncAttributeMaxDynamicSharedMemorySize, SM_TOTAL);

    k0_c2<<<(K + 255) / 256, 256>>>(cbk, K);
    k1_pool_boundary<<<(int)(NS / 16), 128>>>((const float4*)x, (const float4*)bw, bb, bnd_out);
    k2_vq_mma<<<(int)(NS / 128), 256, SM_TOTAL>>>(cbk, (float4*)q_out, idx_out);
    k4_final<<<1, 128>>>(NS * (long)Dd, nTok, loss_out);
}

// round 8
// speedup vs baseline: 1.8947x; 1.0595x over previous
#include <cuda_runtime.h>
#include <cuda_bf16.h>
#include <stdint.h>

#define SPAN   8
#define DIM    192
#define DIM4   48
#define KCB    512
#define MAX_NS 16384
#define BAND   5e-5f
#define LDS    200            // bf16 per smem row (400 B) -> conflict-free ldmatrix

// smem layout (bytes)
#define OFF_AHI  0            // 128 x 400
#define OFF_ALO  51200
#define OFF_B    102400       // 2 stages x (hi 25600 + lo 25600)
#define OFF_C2   204800
#define OFF_SIDX 206848
#define OFF_RED  207360       // 1024 B: float[256] then double[128]
#define OFF_FLAG 208384
#define SM_TOTAL 208400

// -------- device scratch --------
__device__ float         g_pooled[MAX_NS * DIM];
__device__ __nv_bfloat16 g_pah[MAX_NS * DIM];     // pooled hi
__device__ __nv_bfloat16 g_pal[MAX_NS * DIM];     // pooled lo
__device__ __nv_bfloat16 g_cbh[KCB * DIM];        // codebook hi
__device__ __nv_bfloat16 g_cbl[KCB * DIM];        // codebook lo
__device__ float         g_c2[KCB];
__device__ float         g_partial[128];
__device__ unsigned int  g_count;
__device__ unsigned int  g_done;

// ============ helpers ============
__device__ __forceinline__ uint32_t smem_u32(const void* p) {
    uint32_t a;
    asm("{ .reg .u64 t; cvta.to.shared.u64 t, %1; cvt.u32.u64 %0, t; }" : "=r"(a) : "l"(p));
    return a;
}
__device__ __forceinline__ void cp16(uint32_t dst, const void* src) {
    asm volatile("cp.async.cg.shared.global [%0], [%1], 16;" :: "r"(dst), "l"(src) : "memory");
}
#define CP_COMMIT() asm volatile("cp.async.commit_group;" ::: "memory")
#define CP_WAIT1()  asm volatile("cp.async.wait_group 1;" ::: "memory")
#define CP_WAIT0()  asm volatile("cp.async.wait_group 0;" ::: "memory")

__device__ __forceinline__ void ldsm_x4(uint32_t& r0, uint32_t& r1, uint32_t& r2, uint32_t& r3,
                                        uint32_t addr) {
    asm volatile("ldmatrix.sync.aligned.m8n8.x4.shared.b16 {%0,%1,%2,%3}, [%4];"
        : "=r"(r0), "=r"(r1), "=r"(r2), "=r"(r3) : "r"(addr));
}
__device__ __forceinline__ void mma16816(float& d0, float& d1, float& d2, float& d3,
                                         uint32_t a0, uint32_t a1, uint32_t a2, uint32_t a3,
                                         uint32_t b0, uint32_t b1) {
    asm volatile("mma.sync.aligned.m16n8k16.row.col.f32.bf16.bf16.f32 "
        "{%0,%1,%2,%3}, {%4,%5,%6,%7}, {%8,%9}, {%0,%1,%2,%3};"
        : "+f"(d0), "+f"(d1), "+f"(d2), "+f"(d3)
        : "r"(a0), "r"(a1), "r"(a2), "r"(a3), "r"(b0), "r"(b1));
}

__device__ __forceinline__ void ins4(float* s, int* id, float sc, int n) {
    if (sc < s[3]) {
        if (sc < s[0])      { s[3]=s[2];id[3]=id[2]; s[2]=s[1];id[2]=id[1]; s[1]=s[0];id[1]=id[0]; s[0]=sc;id[0]=n; }
        else if (sc < s[1]) { s[3]=s[2];id[3]=id[2]; s[2]=s[1];id[2]=id[1]; s[1]=sc;id[1]=n; }
        else if (sc < s[2]) { s[3]=s[2];id[3]=id[2]; s[2]=sc;id[2]=n; }
        else                { s[3]=sc;id[3]=n; }
    }
}

__device__ __forceinline__ float dot192(const float* a, const float* b) {
    const float4* a4 = (const float4*)a;
    const float4* b4 = (const float4*)b;
    float s = 0.f;
#pragma unroll
    for (int i = 0; i < 48; i++) {
        float4 x = a4[i], y = b4[i];
        s += x.x * y.x + x.y * y.y + x.z * y.z + x.w * y.w;
    }
    return s;
}
__device__ __forceinline__ int exact_argmin(const float* prow, const float* cbk,
                                            const float* c2s) {
    float best = 3.4e38f; int bi = 0;
    for (int n = 0; n < KCB; n++) {
        float sc = c2s[n] - 2.f * dot192(prow, cbk + (size_t)n * DIM);
        if (sc < best) { best = sc; bi = n; }
    }
    return bi;
}
__device__ __forceinline__ int resolve_idx(const float* tS, const int* tI, int segRow,
                                           const float* cbk, const float* c2s) {
    int idx = tI[0];
    if (tS[1] - tS[0] <= BAND) {
        const float* prow = g_pooled + (size_t)segRow * DIM;
        if (tS[3] - tS[0] <= BAND) {
            idx = exact_argmin(prow, cbk, c2s);
        } else {
            int cand[4]; int nc = 0;
            cand[nc++] = tI[0];
            cand[nc++] = tI[1];
            if (tS[2] - tS[0] <= BAND) cand[nc++] = tI[2];
            for (int a = 0; a < nc; a++)
                for (int b = a + 1; b < nc; b++)
                    if (cand[b] < cand[a]) { int t = cand[a]; cand[a] = cand[b]; cand[b] = t; }
            float best = 3.4e38f; int bi = 0;
            for (int a = 0; a < nc; a++) {
                int n = cand[a];
                float sc = c2s[n] - 2.f * dot192(prow, cbk + (size_t)n * DIM);
                if (sc < best) { best = sc; bi = n; }
            }
            idx = bi;
        }
    }
    return idx;
}

// ============================================================
// K0: codebook -> c2 (sequential per row, proven order) + bf16 hi/lo
//     + reset counters
// ============================================================
__global__ void k0_prep(const float* __restrict__ codebook)
{
    int gid = blockIdx.x * blockDim.x + threadIdx.x;   // 96*256 = 24576
    if (gid == 0) { g_count = 0u; g_done = 0u; }

    // elementwise bf16 split
    for (int i = gid; i < KCB * DIM; i += 24576) {
        float v = codebook[i];
        __nv_bfloat16 h = __float2bfloat16(v);
        g_cbh[i] = h;
        g_cbl[i] = __float2bfloat16(v - __bfloat162float(h));
    }

    // c2 rows (same sequential order as proven kernel)
    if (gid < KCB) {
        const float4* row = (const float4*)(codebook + (size_t)gid * DIM);
        float s = 0.f;
#pragma unroll
        for (int i = 0; i < DIM4; i++) {
            float4 v = row[i];
            s += v.x * v.x + v.y * v.y + v.z * v.z + v.w * v.w;
        }
        g_c2[gid] = s;
    }
}

// ============================================================
// K1: pooled (fp32 + bf16 hi/lo) + boundaries
// ============================================================
__global__ void __launch_bounds__(128) k1_pool_boundary(
    const float4* __restrict__ x4, const float4* __restrict__ w4,
    const float* __restrict__ bbias, float* __restrict__ bnd_out)
{
    int tid = threadIdx.x;
    int s_local = tid >> 3;
    int g = tid & 7;
    int s = blockIdx.x * 16 + s_local;

    float4 wv[6];
#pragma unroll
    for (int i = 0; i < 6; i++) wv[i] = __ldg(&w4[g + 8 * i]);
    float4 pool[6];
#pragma unroll
    for (int i = 0; i < 6; i++) pool[i] = make_float4(0.f, 0.f, 0.f, 0.f);

    float part[SPAN];
    int tokBase = s * SPAN;
#pragma unroll
    for (int j = 0; j < SPAN; j++) {
        const float4* row = x4 + (size_t)(tokBase + j) * DIM4;
        float pj = 0.f;
#pragma unroll
        for (int i = 0; i < 6; i++) {
            float4 v = __ldcs(&row[g + 8 * i]);
            pool[i].x += v.x; pool[i].y += v.y; pool[i].z += v.z; pool[i].w += v.w;
            pj += v.x * wv[i].x + v.y * wv[i].y + v.z * wv[i].z + v.w * wv[i].w;
        }
        part[j] = pj;
    }
    float4* pooled4 = (float4*)g_pooled;
#pragma unroll
    for (int i = 0; i < 6; i++) {
        float4 p = pool[i];
        p.x *= 0.125f; p.y *= 0.125f; p.z *= 0.125f; p.w *= 0.125f;
        pooled4[(size_t)s * DIM4 + g + 8 * i] = p;

        // bf16 hi/lo (8 bytes each stream)
        __nv_bfloat16 h0 = __float2bfloat16(p.x);
        __nv_bfloat16 h1 = __float2bfloat16(p.y);
        __nv_bfloat16 h2 = __float2bfloat16(p.z);
        __nv_bfloat16 h3 = __float2bfloat16(p.w);
        __nv_bfloat162 ha(h0, h1), hb(h2, h3);
        __nv_bfloat162 la(__float2bfloat16(p.x - __bfloat162float(h0)),
                          __float2bfloat16(p.y - __bfloat162float(h1)));
        __nv_bfloat162 lb(__float2bfloat16(p.z - __bfloat162float(h2)),
                          __float2bfloat16(p.w - __bfloat162float(h3)));
        uint2 uh, ul;
        uh.x = *(uint32_t*)&ha; uh.y = *(uint32_t*)&hb;
        ul.x = *(uint32_t*)&la; ul.y = *(uint32_t*)&lb;
        size_t boff = (size_t)s * 384 + (size_t)(g + 8 * i) * 8;
        *(uint2*)((char*)g_pah + boff) = uh;
        *(uint2*)((char*)g_pal + boff) = ul;
    }

#pragma unroll
    for (int m = 1; m < 8; m <<= 1) {
#pragma unroll
        for (int j = 0; j < SPAN; j++)
            part[j] += __shfl_xor_sync(0xffffffffu, part[j], m);
    }
    float bb = __ldg(bbias);
    float b = (part[g] + bb > 0.f) ? 1.f : 0.f;
    bnd_out[tokBase + g] = b;
    unsigned bal = __ballot_sync(0xffffffffu, b > 0.f);
    if ((tid & 31) == 0) atomicAdd(&g_count, (unsigned)__popc(bal));
}

// ---- cp.async staging ----
__device__ __forceinline__ void stageA(uint32_t sb, int tid, int segBase) {
    const char* srcH = (const char*)g_pah + (size_t)segBase * 384;
    const char* srcL = (const char*)g_pal + (size_t)segBase * 384;
#pragma unroll
    for (int it = 0; it < 12; it++) {
        int item = tid + it * 256;        // 3072 = 128 rows x 24 chunks
        int row = item / 24, ch = item - row * 24;
        uint32_t d = (uint32_t)(row * 400 + ch * 16);
        cp16(sb + OFF_AHI + d, srcH + row * 384 + ch * 16);
        cp16(sb + OFF_ALO + d, srcL + row * 384 + ch * 16);
    }
}
__device__ __forceinline__ void stageB(uint32_t sb, int tid, int chunk, int buf) {
    const char* srcH = (const char*)g_cbh + (size_t)chunk * 64 * 384;
    const char* srcL = (const char*)g_cbl + (size_t)chunk * 64 * 384;
    uint32_t base = sb + OFF_B + (uint32_t)buf * 51200;
#pragma unroll
    for (int it = 0; it < 6; it++) {
        int item = tid + it * 256;        // 1536 = 64 rows x 24 chunks
        int row = item / 24, ch = item - row * 24;
        uint32_t d = (uint32_t)(row * 400 + ch * 16);
        cp16(base + d,         srcH + row * 384 + ch * 16);
        cp16(base + 25600 + d, srcL + row * 384 + ch * 16);
    }
}

// ============================================================
// K2 v6: HMMA VQ, cp.async double-buffered B (8 chunks x 64 codes),
//        pre-converted bf16 operands, guarded argmin, fused scatter,
//        fused last-block loss finalize.
// ============================================================
__global__ void __launch_bounds__(256, 1) k2_vq_mma(
    const float* __restrict__ cbk,
    float4* __restrict__ q4,
    float*  __restrict__ idx_out,
    float*  __restrict__ loss_out,
    long nsD, long nTok)
{
    extern __shared__ char smem[];
    uint32_t sb = smem_u32(smem);
    int tid  = threadIdx.x;
    int warp = tid >> 5;
    int lane = tid & 31;
    int segBase = blockIdx.x * 128;

    float* c2s  = (float*)(smem + OFF_C2);
    int*   sidx = (int*)(smem + OFF_SIDX);
    float* red  = (float*)(smem + OFF_RED);

    // prefetch A + B chunk 0
    stageA(sb, tid, segBase);
    stageB(sb, tid, 0, 0);
    CP_COMMIT();

    for (int i = tid; i < KCB; i += 256) c2s[i] = g_c2[i];

    float tS0[4], tS1[4]; int tI0[4], tI1[4];
#pragma unroll
    for (int j = 0; j < 4; j++) { tS0[j] = 3.4e38f; tS1[j] = 3.4e38f; tI0[j] = 0; tI1[j] = 0; }

    uint32_t aAddrH = sb + OFF_AHI + (uint32_t)((warp * 16 + (lane & 15)) * LDS + ((lane >> 4) << 3)) * 2;
    uint32_t aAddrL = aAddrH + (OFF_ALO - OFF_AHI);
    // B x4 lane address: matrix = lane>>3; row = tp*16 + (lane&7) + ((lane>>4)&1)*8
    uint32_t bRow = (uint32_t)((lane & 7) + ((lane >> 4) & 1) * 8);
    uint32_t bColH = (uint32_t)(((lane >> 3) & 1) * 8);

    for (int c = 0; c < 8; c++) {
        if (c < 7) { stageB(sb, tid, c + 1, (c + 1) & 1); CP_COMMIT(); CP_WAIT1(); }
        else       { CP_WAIT0(); }
        __syncthreads();

        uint32_t bBase = sb + OFF_B + (uint32_t)(c & 1) * 51200;
        float acc[8][4];
#pragma unroll
        for (int nt = 0; nt < 8; nt++)
#pragma unroll
            for (int j = 0; j < 4; j++) acc[nt][j] = 0.f;

#pragma unroll
        for (int kt = 0; kt < 12; kt++) {
            uint32_t kb = (uint32_t)(kt * 16) * 2;
            uint32_t ah0, ah1, ah2, ah3, al0, al1, al2, al3;
            ldsm_x4(ah0, ah1, ah2, ah3, aAddrH + kb);
            ldsm_x4(al0, al1, al2, al3, aAddrL + kb);
#pragma unroll
            for (int tp = 0; tp < 4; tp++) {
                uint32_t bAddr = bBase + ((uint32_t)(tp * 16) + bRow) * (LDS * 2)
                               + (kb + bColH * 2);
                uint32_t bh0, bh1, bh2, bh3, bl0, bl1, bl2, bl3;
                ldsm_x4(bh0, bh1, bh2, bh3, bAddr);
                ldsm_x4(bl0, bl1, bl2, bl3, bAddr + 25600);
                int n0 = tp * 2, n1 = tp * 2 + 1;
                mma16816(acc[n0][0], acc[n0][1], acc[n0][2], acc[n0][3], ah0, ah1, ah2, ah3, bh0, bh1);
                mma16816(acc[n0][0], acc[n0][1], acc[n0][2], acc[n0][3], al0, al1, al2, al3, bh0, bh1);
                mma16816(acc[n0][0], acc[n0][1], acc[n0][2], acc[n0][3], ah0, ah1, ah2, ah3, bl0, bl1);
                mma16816(acc[n1][0], acc[n1][1], acc[n1][2], acc[n1][3], ah0, ah1, ah2, ah3, bh2, bh3);
                mma16816(acc[n1][0], acc[n1][1], acc[n1][2], acc[n1][3], al0, al1, al2, al3, bh2, bh3);
                mma16816(acc[n1][0], acc[n1][1], acc[n1][2], acc[n1][3], ah0, ah1, ah2, ah3, bl2, bl3);
            }
        }

#pragma unroll
        for (int nt = 0; nt < 8; nt++) {
            int n0 = c * 64 + nt * 8 + 2 * (lane & 3);
            float cA = c2s[n0], cB = c2s[n0 + 1];
            ins4(tS0, tI0, cA - 2.f * acc[nt][0], n0);
            ins4(tS0, tI0, cB - 2.f * acc[nt][1], n0 + 1);
            ins4(tS1, tI1, cA - 2.f * acc[nt][2], n0);
            ins4(tS1, tI1, cB - 2.f * acc[nt][3], n0 + 1);
        }
        __syncthreads();
    }

    // merge top-4 across the 4 lanes of each quad
#pragma unroll
    for (int m = 1; m <= 2; m <<= 1) {
        float os[4]; int oi[4];
#pragma unroll
        for (int j = 0; j < 4; j++) {
            os[j] = __shfl_xor_sync(0xffffffffu, tS0[j], m);
            oi[j] = __shfl_xor_sync(0xffffffffu, tI0[j], m);
        }
#pragma unroll
        for (int j = 0; j < 4; j++) ins4(tS0, tI0, os[j], oi[j]);
#pragma unroll
        for (int j = 0; j < 4; j++) {
            os[j] = __shfl_xor_sync(0xffffffffu, tS1[j], m);
            oi[j] = __shfl_xor_sync(0xffffffffu, tI1[j], m);
        }
#pragma unroll
        for (int j = 0; j < 4; j++) ins4(tS1, tI1, os[j], oi[j]);
    }

    if ((lane & 3) == 0) {
        int r0 = warp * 16 + (lane >> 2);
        int r1 = r0 + 8;
        sidx[r0] = resolve_idx(tS0, tI0, segBase + r0, cbk, c2s);
        sidx[r1] = resolve_idx(tS1, tI1, segBase + r1, cbk, c2s);
    }
    __syncthreads();

    // ---- fused scatter ----
    {
        int s_local = tid >> 3;
        int g = tid & 7;
        const float4* pooled4 = (const float4*)g_pooled;
        const float4* cb4 = (const float4*)cbk;
        float ssum = 0.f;
#pragma unroll
        for (int p = 0; p < 4; p++) {
            int sl = p * 32 + s_local;
            int s  = segBase + sl;
            int ci = sidx[sl];
            float4 cc[6];
#pragma unroll
            for (int i = 0; i < 6; i++) {
                cc[i] = __ldg(&cb4[(size_t)ci * DIM4 + g + 8 * i]);
                float4 pv = __ldg(&pooled4[(size_t)s * DIM4 + g + 8 * i]);
                float dx = cc[i].x - pv.x, dy = cc[i].y - pv.y,
                      dz = cc[i].z - pv.z, dw = cc[i].w - pv.w;
                ssum += dx * dx + dy * dy + dz * dz + dw * dw;
            }
            int tokBase = s * SPAN;
#pragma unroll
            for (int j = 0; j < SPAN; j++) {
                float4* dst = q4 + (size_t)(tokBase + j) * DIM4;
#pragma unroll
                for (int i = 0; i < 6; i++)
                    __stcs(&dst[g + 8 * i], cc[i]);
            }
            idx_out[tokBase + g] = (float)ci;
        }
        red[tid] = ssum;
    }
    __syncthreads();
#pragma unroll
    for (int st = 128; st > 0; st >>= 1) {
        if (tid < st) red[tid] += red[tid + st];
        __syncthreads();
    }
    if (tid == 0) g_partial[blockIdx.x] = red[0];

    // ---- fused finalize: last block computes the loss ----
    __threadfence();
    if (tid == 0) {
        unsigned v = atomicAdd(&g_done, 1u);
        *(int*)(smem + OFF_FLAG) = (v == gridDim.x - 1) ? 1 : 0;
    }
    __syncthreads();
    if (*(int*)(smem + OFF_FLAG)) {
        double* sd = (double*)(smem + OFF_RED);
        if (tid < 128) sd[tid] = (double)g_partial[tid];
        __syncthreads();
#pragma unroll
        for (int st = 64; st > 0; st >>= 1) {
            if (tid < st) sd[tid] += sd[tid + st];
            __syncthreads();
        }
        if (tid == 0) {
            double e_latent = sd[0] / (double)nsD;
            double bmean = (double)g_count / (double)nTok;
            double d = bmean - 0.125;
            *loss_out = (float)(0.25 * e_latent + 0.01 * d * d);
        }
    }
}

// ============================================================
// launch
// inputs: x [B,T,D] f32, codebook [K,D] f32, boundary_w [D] f32, boundary_b [1] f32
// output (f32 concat): q_out | total_loss | idx_out | boundaries
// ============================================================
extern "C" void kernel_launch(void* const* d_in, const int* in_sizes, int n_in,
                              void* d_out, int out_size)
{
    const float* x   = (const float*)d_in[0];
    const float* cbk = (const float*)d_in[1];
    const float* bw  = (const float*)d_in[2];
    const float* bb  = (const float*)d_in[3];

    int  Dd   = in_sizes[2];                 // 192
    long nTok = (long)in_sizes[0] / Dd;      // 131072
    long NS   = nTok / SPAN;                 // 16384

    float* q_out    = (float*)d_out;
    float* loss_out = q_out + nTok * (long)Dd;
    float* idx_out  = loss_out + 1;
    float* bnd_out  = idx_out + nTok;

    cudaFuncSetAttribute(k2_vq_mma, cudaFuncAttributeMaxDynamicSharedMemorySize, SM_TOTAL);

    k0_prep<<<96, 256>>>(cbk);
    k1_pool_boundary<<<(int)(NS / 16), 128>>>((const float4*)x, (const float4*)bw, bb, bnd_out);
    k2_vq_mma<<<(int)(NS / 128), 256, SM_TOTAL>>>(cbk, (float4*)q_out, idx_out,
                                                  loss_out, NS * (long)Dd, nTok);
}